// round 2
// baseline (speedup 1.0000x reference)
#include <cuda_runtime.h>
#include <math.h>

#define NBATCH 64
#define NPTSB  1024
#define NP     65536
#define KNN    16

// ---------------- scratch (static __device__, no allocs) ----------------
__device__ float g_dist[(size_t)NP * NPTSB];   // 256 MB distance scores
__device__ int   g_idx[NP * KNN];              // knn indices (within batch)
__device__ float g_feat[NP * 192];             // [x1 | x2 | x3] concat, stride 192
__device__ float g_A[NP * 64];                 // point-level A = X@(W1a-W1b)+b1
__device__ float g_P[NP * 64];                 // point-level P = X@W1b
__device__ float g_h1[NP * 128];
__device__ float g_h2[NP * 64];
__device__ float g_h3[NP * 32];

// selector for buffers usable from host-launched templated GEMM
__device__ __forceinline__ float* buf_sel(int s) {
  switch (s) {
    case 0: return g_feat;
    case 1: return g_h1;
    case 2: return g_h2;
    case 3: return g_h3;
  }
  return 0;
}

// ---------------- KNN: distance kernels ----------------
// score(i,j) = |xj|^2 - 2 xi.xj   (same per-row ordering as full sq distance)

__global__ __launch_bounds__(256) void dist1_kernel(const float* __restrict__ x) {
  int t = blockIdx.x * 256 + threadIdx.x;      // 16,777,216 threads
  int b = t >> 18;
  int i = (t >> 8) & 1023;
  int j = (t & 255) << 2;
  float xi = x[(b << 10) + i];
  float4 xj = *(const float4*)&x[(b << 10) + j];
  float4 s;
  s.x = xj.x * (xj.x - 2.0f * xi);
  s.y = xj.y * (xj.y - 2.0f * xi);
  s.z = xj.z * (xj.z - 2.0f * xi);
  s.w = xj.w * (xj.w - 2.0f * xi);
  *(float4*)&g_dist[((size_t)((b << 10) + i) << 10) + j] = s;
}

// 64-dim distance GEMM: grid (16,16,64), block 256, 64x64 tile, K=64 one shot
__global__ __launch_bounds__(256) void dist64_kernel(int featOff) {
  __shared__ float xi_s[64][68];
  __shared__ float xj_s[64][68];
  __shared__ float sqj[64];
  int tid = threadIdx.x;
  int b = blockIdx.z;
  int i0 = blockIdx.y * 64;
  int j0 = blockIdx.x * 64;
  const float* Xb = g_feat + (size_t)(b << 10) * 192 + featOff;

  for (int t = tid; t < 4096; t += 256) {
    int rr = t >> 6, dd = t & 63;
    xi_s[rr][dd] = Xb[(size_t)(i0 + rr) * 192 + dd];
    xj_s[rr][dd] = Xb[(size_t)(j0 + rr) * 192 + dd];
  }
  __syncthreads();
  if (tid < 64) {
    float s = 0.f;
#pragma unroll
    for (int d = 0; d < 64; d++) { float v = xj_s[tid][d]; s += v * v; }
    sqj[tid] = s;
  }
  __syncthreads();

  int rb = tid & 15, cb = tid >> 4;
  int r0 = rb * 4, c0 = cb * 4;
  float acc[4][4] = {};
#pragma unroll
  for (int k = 0; k < 64; k += 4) {
    float a[4][4], bm[4][4];
#pragma unroll
    for (int i = 0; i < 4; i++) {
      float4 v = *(const float4*)&xi_s[r0 + i][k];
      a[i][0] = v.x; a[i][1] = v.y; a[i][2] = v.z; a[i][3] = v.w;
      float4 w = *(const float4*)&xj_s[c0 + i][k];
      bm[i][0] = w.x; bm[i][1] = w.y; bm[i][2] = w.z; bm[i][3] = w.w;
    }
#pragma unroll
    for (int kk = 0; kk < 4; kk++)
#pragma unroll
      for (int i = 0; i < 4; i++)
#pragma unroll
        for (int j = 0; j < 4; j++)
          acc[i][j] += a[i][kk] * bm[j][kk];
  }
#pragma unroll
  for (int i = 0; i < 4; i++) {
    float4 s4;
    s4.x = sqj[c0 + 0] - 2.0f * acc[i][0];
    s4.y = sqj[c0 + 1] - 2.0f * acc[i][1];
    s4.z = sqj[c0 + 2] - 2.0f * acc[i][2];
    s4.w = sqj[c0 + 3] - 2.0f * acc[i][3];
    *(float4*)&g_dist[(((size_t)(b << 10) + i0 + r0 + i) << 10) + j0 + c0] = s4;
  }
}

// ---------------- top-16 (iterative argmin, tie -> smaller index) ----------------
__global__ __launch_bounds__(256) void topk_kernel() {
  int row = blockIdx.x;  // 0..65535
  __shared__ float ds[1024];
  __shared__ float rv[8];
  __shared__ int   ri[8];
  int tid = threadIdx.x;
  const float* src = g_dist + (size_t)row * 1024;
  for (int t = tid; t < 1024; t += 256) ds[t] = src[t];
  __syncthreads();

  for (int it = 0; it < 16; it++) {
    float bv = 3.402823466e38f;
    int bi = 1 << 20;
    for (int t = tid; t < 1024; t += 256) {
      float v = ds[t];
      if (v < bv) { bv = v; bi = t; }   // ascending t => earliest index kept on ties
    }
#pragma unroll
    for (int o = 16; o; o >>= 1) {
      float ov = __shfl_down_sync(0xffffffffu, bv, o);
      int   oi = __shfl_down_sync(0xffffffffu, bi, o);
      if (ov < bv || (ov == bv && oi < bi)) { bv = ov; bi = oi; }
    }
    if ((tid & 31) == 0) { rv[tid >> 5] = bv; ri[tid >> 5] = bi; }
    __syncthreads();
    if (tid == 0) {
#pragma unroll
      for (int w = 1; w < 8; w++)
        if (rv[w] < bv || (rv[w] == bv && ri[w] < bi)) { bv = rv[w]; bi = ri[w]; }
      g_idx[row * 16 + it] = bi;
      ds[bi] = 3.402823466e38f;
    }
    __syncthreads();
  }
}

// ---------------- point-level A/P precompute ----------------
// conv1 (d_in = 1): trivially elementwise
__global__ __launch_bounds__(256) void prec1_kernel(const float* __restrict__ x,
                                                    const float* __restrict__ w1,
                                                    const float* __restrict__ b1) {
  int t = blockIdx.x * 256 + threadIdx.x;  // NP*16 threads
  int i = t >> 4;
  int c = (t & 15) << 2;
  float xi = x[i];
  float4 wa = *(const float4*)&w1[c];
  float4 wb = *(const float4*)&w1[64 + c];
  float4 bb = *(const float4*)&b1[c];
  float4 A, P;
  A.x = xi * (wa.x - wb.x) + bb.x;  P.x = xi * wb.x;
  A.y = xi * (wa.y - wb.y) + bb.y;  P.y = xi * wb.y;
  A.z = xi * (wa.z - wb.z) + bb.z;  P.z = xi * wb.z;
  A.w = xi * (wa.w - wb.w) + bb.w;  P.w = xi * wb.w;
  *(float4*)&g_A[(size_t)i * 64 + c] = A;
  *(float4*)&g_P[(size_t)i * 64 + c] = P;
}

// conv2/3 (d_in = 64): dual GEMM, 64-row blocks, K chunked by 32
__global__ __launch_bounds__(256) void prec64_kernel(int featOff,
                                                     const float* __restrict__ w1,
                                                     const float* __restrict__ b1) {
  __shared__ float xs[64][36];
  __shared__ float wd[32][64];
  __shared__ float wb[32][64];
  int tid = threadIdx.x;
  int row0 = blockIdx.x * 64;
  int rb = tid & 15, cb = tid >> 4;
  int r0 = rb * 4, c0 = cb * 4;
  float accA[4][4] = {}, accP[4][4] = {};

  for (int kc = 0; kc < 64; kc += 32) {
    __syncthreads();
    for (int t = tid; t < 2048; t += 256) {
      int rr = t >> 5, dd = t & 31;
      xs[rr][dd] = g_feat[(size_t)(row0 + rr) * 192 + featOff + kc + dd];
    }
    for (int t = tid; t < 2048; t += 256) {
      int kk = t >> 6, cc = t & 63;
      float bw = w1[(size_t)(64 + kc + kk) * 64 + cc];
      wb[kk][cc] = bw;
      wd[kk][cc] = w1[(size_t)(kc + kk) * 64 + cc] - bw;
    }
    __syncthreads();
#pragma unroll
    for (int k = 0; k < 32; k += 4) {
      float a[4][4];
#pragma unroll
      for (int i = 0; i < 4; i++) {
        float4 v = *(const float4*)&xs[r0 + i][k];
        a[i][0] = v.x; a[i][1] = v.y; a[i][2] = v.z; a[i][3] = v.w;
      }
#pragma unroll
      for (int kk = 0; kk < 4; kk++)
#pragma unroll
        for (int cc = 0; cc < 4; cc++) {
          float wdv = wd[k + kk][c0 + cc];
          float wbv = wb[k + kk][c0 + cc];
#pragma unroll
          for (int i = 0; i < 4; i++) {
            accA[i][cc] += a[i][kk] * wdv;
            accP[i][cc] += a[i][kk] * wbv;
          }
        }
    }
  }
#pragma unroll
  for (int i = 0; i < 4; i++)
#pragma unroll
    for (int cc = 0; cc < 4; cc++) {
      int r = row0 + r0 + i, c = c0 + cc;
      g_A[(size_t)r * 64 + c] = accA[i][cc] + b1[c];
      g_P[(size_t)r * 64 + c] = accP[i][cc];
    }
}

// ---------------- fused edge kernel ----------------
// per block: 8 points x 16 edges = 128 h1 rows built in smem, then
// out[p][c] = max_e ( h1[p*16+e] @ W2 )[c] + b2[c]
__global__ __launch_bounds__(256) void edge_kernel(const float* __restrict__ w2,
                                                   const float* __restrict__ b2,
                                                   int outOff) {
  __shared__ float h1s[128][68];
  __shared__ union { float w2c[32][64]; float red[32][64]; } u;
  int tid = threadIdx.x;
  int p0 = blockIdx.x * 8;

  // build h1 rows: h1[r] = relu(A[i(r)] + P[j(r)])
  {
    int r = tid >> 1;
    int d0 = (tid & 1) * 32;
    int p = r >> 4, e = r & 15;
    int gi = p0 + p;
    int b = gi >> 10;
    int j = g_idx[gi * 16 + e];
    const float* Pr = g_P + ((size_t)((b << 10) + j)) * 64 + d0;
    const float* Ar = g_A + (size_t)gi * 64 + d0;
#pragma unroll
    for (int dd = 0; dd < 32; dd += 4) {
      float4 pv = *(const float4*)(Pr + dd);
      float4 av = *(const float4*)(Ar + dd);
      float4 h;
      h.x = fmaxf(av.x + pv.x, 0.f);
      h.y = fmaxf(av.y + pv.y, 0.f);
      h.z = fmaxf(av.z + pv.z, 0.f);
      h.w = fmaxf(av.w + pv.w, 0.f);
      *(float4*)&h1s[r][d0 + dd] = h;
    }
  }

  // GEMM: 128x64, K=64 in two 32-chunks of W2 (union smem)
  int rb = tid & 15, cb = tid >> 4;
  int c0 = cb * 4;
  float acc[8][4] = {};
  for (int kc = 0; kc < 64; kc += 32) {
    __syncthreads();
    for (int t = tid; t < 2048; t += 256) {
      int kk = t >> 6, cc = t & 63;
      u.w2c[kk][cc] = w2[(size_t)(kc + kk) * 64 + cc];
    }
    __syncthreads();
#pragma unroll
    for (int k = 0; k < 32; k += 4) {
      float a[8][4];
#pragma unroll
      for (int i = 0; i < 8; i++) {
        int rr = (i < 4) ? (rb * 4 + i) : (64 + rb * 4 + i - 4);
        float4 v = *(const float4*)&h1s[rr][kc + k];
        a[i][0] = v.x; a[i][1] = v.y; a[i][2] = v.z; a[i][3] = v.w;
      }
#pragma unroll
      for (int kk = 0; kk < 4; kk++)
#pragma unroll
        for (int cc = 0; cc < 4; cc++) {
          float wv = u.w2c[k + kk][c0 + cc];
#pragma unroll
          for (int i = 0; i < 8; i++) acc[i][cc] += a[i][kk] * wv;
        }
    }
  }
  __syncthreads();  // all W2 reads done -> union becomes red[]

  // partial max: low rows rb*4..+3 (point rb/4), high rows 64+rb*4..+3 (point 4+rb/4)
  {
    float mlo[4], mhi[4];
#pragma unroll
    for (int cc = 0; cc < 4; cc++) {
      float vl = acc[0][cc], vh = acc[4][cc];
#pragma unroll
      for (int i = 1; i < 4; i++) { vl = fmaxf(vl, acc[i][cc]); vh = fmaxf(vh, acc[4 + i][cc]); }
      mlo[cc] = vl; mhi[cc] = vh;
    }
#pragma unroll
    for (int cc = 0; cc < 4; cc++) {
      u.red[rb][c0 + cc] = mlo[cc];
      u.red[16 + rb][c0 + cc] = mhi[cc];
    }
  }
  __syncthreads();

  for (int t = tid; t < 512; t += 256) {
    int pp = t >> 6, c = t & 63;
    int base = (pp < 4) ? (pp * 4) : (16 + (pp - 4) * 4);
    float v = u.red[base][c];
#pragma unroll
    for (int q = 1; q < 4; q++) v = fmaxf(v, u.red[base + q][c]);
    g_feat[(size_t)(p0 + pp) * 192 + outOff + c] = v + b2[c];
  }
}

// ---------------- MLP head GEMMs ----------------
template <int K, int N, bool RELU>
__global__ __launch_bounds__(256) void gemm_kernel(int xsel, int sx,
                                                   const float* __restrict__ W,
                                                   const float* __restrict__ bias,
                                                   int osel, int so) {
  constexpr int CT = N / 16;
  __shared__ float xs[64][36];
  __shared__ float ws[32][N];
  const float* X = buf_sel(xsel);
  float* out = buf_sel(osel);
  int tid = threadIdx.x;
  int row0 = blockIdx.x * 64;
  int rb = tid & 15, cb = tid >> 4;
  int r0 = rb * 4, c0 = cb * CT;
  float acc[4][CT];
#pragma unroll
  for (int i = 0; i < 4; i++)
#pragma unroll
    for (int c = 0; c < CT; c++) acc[i][c] = 0.f;

  for (int kc = 0; kc < K; kc += 32) {
    __syncthreads();
    for (int t = tid; t < 2048; t += 256) {
      int rr = t >> 5, dd = t & 31;
      xs[rr][dd] = X[(size_t)(row0 + rr) * sx + kc + dd];
    }
    for (int t = tid; t < 32 * N; t += 256) {
      int kk = t / N, cc = t % N;
      ws[kk][cc] = W[(size_t)(kc + kk) * N + cc];
    }
    __syncthreads();
#pragma unroll
    for (int k = 0; k < 32; k += 4) {
      float a[4][4];
#pragma unroll
      for (int i = 0; i < 4; i++) {
        float4 v = *(const float4*)&xs[r0 + i][k];
        a[i][0] = v.x; a[i][1] = v.y; a[i][2] = v.z; a[i][3] = v.w;
      }
#pragma unroll
      for (int kk = 0; kk < 4; kk++)
#pragma unroll
        for (int cc = 0; cc < CT; cc++) {
          float wv = ws[k + kk][c0 + cc];
#pragma unroll
          for (int i = 0; i < 4; i++) acc[i][cc] += a[i][kk] * wv;
        }
    }
  }
#pragma unroll
  for (int i = 0; i < 4; i++)
#pragma unroll
    for (int cc = 0; cc < CT; cc++) {
      float v = acc[i][cc] + bias[c0 + cc];
      if (RELU) v = fmaxf(v, 0.f);
      out[(size_t)(row0 + r0 + i) * so + c0 + cc] = v;
    }
}

// final layer (32 -> 2) + log_softmax
__global__ __launch_bounds__(256) void final_kernel(const float* __restrict__ w4,
                                                    const float* __restrict__ b4,
                                                    float* __restrict__ out) {
  int i = blockIdx.x * 256 + threadIdx.x;  // 65536
  const float* h = g_h3 + (size_t)i * 32;
  float z0 = b4[0], z1 = b4[1];
#pragma unroll
  for (int k = 0; k < 32; k += 4) {
    float4 v = *(const float4*)&h[k];
    z0 += v.x * w4[(k + 0) * 2 + 0];  z1 += v.x * w4[(k + 0) * 2 + 1];
    z0 += v.y * w4[(k + 1) * 2 + 0];  z1 += v.y * w4[(k + 1) * 2 + 1];
    z0 += v.z * w4[(k + 2) * 2 + 0];  z1 += v.z * w4[(k + 2) * 2 + 1];
    z0 += v.w * w4[(k + 3) * 2 + 0];  z1 += v.w * w4[(k + 3) * 2 + 1];
  }
  float m = fmaxf(z0, z1);
  float l = m + logf(expf(z0 - m) + expf(z1 - m));
  out[2 * i + 0] = z0 - l;
  out[2 * i + 1] = z1 - l;
}

// ---------------- launch ----------------
extern "C" void kernel_launch(void* const* d_in, const int* in_sizes, int n_in,
                              void* d_out, int out_size) {
  const float* x    = (const float*)d_in[0];
  const float* c1w1 = (const float*)d_in[1];
  const float* c1b1 = (const float*)d_in[2];
  const float* c1w2 = (const float*)d_in[3];
  const float* c1b2 = (const float*)d_in[4];
  const float* c2w1 = (const float*)d_in[5];
  const float* c2b1 = (const float*)d_in[6];
  const float* c2w2 = (const float*)d_in[7];
  const float* c2b2 = (const float*)d_in[8];
  const float* c3w1 = (const float*)d_in[9];
  const float* c3b1 = (const float*)d_in[10];
  const float* c3w2 = (const float*)d_in[11];
  const float* c3b2 = (const float*)d_in[12];
  const float* mw1  = (const float*)d_in[13];
  const float* mb1  = (const float*)d_in[14];
  const float* mw2  = (const float*)d_in[15];
  const float* mb2  = (const float*)d_in[16];
  const float* mw3  = (const float*)d_in[17];
  const float* mb3  = (const float*)d_in[18];
  const float* mw4  = (const float*)d_in[19];
  const float* mb4  = (const float*)d_in[20];
  float* out = (float*)d_out;

  // ---- EdgeConv 1 (d_in = 1) ----
  dist1_kernel<<<65536, 256>>>(x);
  topk_kernel<<<NP, 256>>>();
  prec1_kernel<<<4096, 256>>>(x, c1w1, c1b1);
  edge_kernel<<<NP / 8, 256>>>(c1w2, c1b2, 0);

  // ---- EdgeConv 2 (on x1, d_in = 64) ----
  dist64_kernel<<<dim3(16, 16, 64), 256>>>(0);
  topk_kernel<<<NP, 256>>>();
  prec64_kernel<<<1024, 256>>>(0, c2w1, c2b1);
  edge_kernel<<<NP / 8, 256>>>(c2w2, c2b2, 64);

  // ---- EdgeConv 3 (on x2, d_in = 64) ----
  dist64_kernel<<<dim3(16, 16, 64), 256>>>(64);
  topk_kernel<<<NP, 256>>>();
  prec64_kernel<<<1024, 256>>>(64, c3w1, c3b1);
  edge_kernel<<<NP / 8, 256>>>(c3w2, c3b2, 128);

  // ---- MLP head ----
  gemm_kernel<192, 128, true><<<1024, 256>>>(0, 192, mw1, mb1, 1, 128);
  gemm_kernel<128, 64, true><<<1024, 256>>>(1, 128, mw2, mb2, 2, 64);
  gemm_kernel<64, 32, true><<<1024, 256>>>(2, 64, mw3, mb3, 3, 32);
  final_kernel<<<256, 256>>>(mw4, mb4, out);
}

// round 3
// speedup vs baseline: 2.1492x; 2.1492x over previous
#include <cuda_runtime.h>
#include <math.h>

#define NBATCH 64
#define NPTSB  1024
#define NP     65536
#define KNN    16

// ---------------- scratch (static __device__, no allocs) ----------------
__device__ float g_dist[(size_t)NP * NPTSB];   // 256 MB distance scores
__device__ int   g_idx[NP * KNN];              // knn indices (within batch)
__device__ float g_feat[NP * 192];             // [x1 | x2 | x3] concat, stride 192
__device__ float g_A[NP * 64];                 // point-level A = X@(W1a-W1b)+b1
__device__ float g_P[NP * 64];                 // point-level P = X@W1b
__device__ float g_h1[NP * 128];
__device__ float g_h2[NP * 64];
__device__ float g_h3[NP * 32];

__device__ __forceinline__ float* buf_sel(int s) {
  switch (s) {
    case 0: return g_feat;
    case 1: return g_h1;
    case 2: return g_h2;
    case 3: return g_h3;
  }
  return 0;
}

// ---------------- KNN distance, d_in = 1 ----------------
// score(i,j) = |xj|^2 - 2 xi.xj  (row-constant |xi|^2 dropped; ordering preserved)
__global__ __launch_bounds__(256) void dist1_kernel(const float* __restrict__ x) {
  int t = blockIdx.x * 256 + threadIdx.x;
  int b = t >> 18;
  int i = (t >> 8) & 1023;
  int j = (t & 255) << 2;
  float xi = x[(b << 10) + i];
  float4 xj = *(const float4*)&x[(b << 10) + j];
  float4 s;
  s.x = xj.x * (xj.x - 2.0f * xi);
  s.y = xj.y * (xj.y - 2.0f * xi);
  s.z = xj.z * (xj.z - 2.0f * xi);
  s.w = xj.w * (xj.w - 2.0f * xi);
  *(float4*)&g_dist[((size_t)((b << 10) + i) << 10) + j] = s;
}

// ---------------- KNN distance GEMM, d_in = 64 ----------------
// 128x128 output tile, 8x8 register micro-tile, transposed smem operands.
__global__ __launch_bounds__(256, 2) void dist64_kernel(int featOff) {
  __shared__ float xiT[32][132];
  __shared__ float xjT[32][132];
  __shared__ float sqj[128];
  int tid = threadIdx.x;
  int b = blockIdx.z;
  int i0 = blockIdx.y << 7;
  int j0 = blockIdx.x << 7;
  const float* Xb = g_feat + ((size_t)b << 10) * 192 + featOff;

  int rb = tid & 15, cb = tid >> 4;
  int r0 = rb << 3, c0 = cb << 3;
  float acc[8][8];
#pragma unroll
  for (int i = 0; i < 8; i++)
#pragma unroll
    for (int j = 0; j < 8; j++) acc[i][j] = 0.f;
  float sq = 0.f;

  for (int kc = 0; kc < 64; kc += 32) {
    __syncthreads();
#pragma unroll
    for (int t = tid; t < 1024; t += 256) {
      int r = t >> 3, dg = (t & 7) << 2;
      float4 vi = *(const float4*)&Xb[(size_t)(i0 + r) * 192 + kc + dg];
      xiT[dg + 0][r] = vi.x; xiT[dg + 1][r] = vi.y;
      xiT[dg + 2][r] = vi.z; xiT[dg + 3][r] = vi.w;
      float4 vj = *(const float4*)&Xb[(size_t)(j0 + r) * 192 + kc + dg];
      xjT[dg + 0][r] = vj.x; xjT[dg + 1][r] = vj.y;
      xjT[dg + 2][r] = vj.z; xjT[dg + 3][r] = vj.w;
    }
    __syncthreads();
    if (tid < 128) {
#pragma unroll
      for (int d = 0; d < 32; d++) { float u = xjT[d][tid]; sq += u * u; }
    }
#pragma unroll
    for (int k = 0; k < 32; k++) {
      float a[8], bv[8];
      *(float4*)&a[0]  = *(const float4*)&xiT[k][r0];
      *(float4*)&a[4]  = *(const float4*)&xiT[k][r0 + 4];
      *(float4*)&bv[0] = *(const float4*)&xjT[k][c0];
      *(float4*)&bv[4] = *(const float4*)&xjT[k][c0 + 4];
#pragma unroll
      for (int i = 0; i < 8; i++)
#pragma unroll
        for (int j = 0; j < 8; j++) acc[i][j] += a[i] * bv[j];
    }
  }
  if (tid < 128) sqj[tid] = sq;
  __syncthreads();
#pragma unroll
  for (int i = 0; i < 8; i++) {
    float4 o0, o1;
    o0.x = sqj[c0 + 0] - 2.f * acc[i][0];
    o0.y = sqj[c0 + 1] - 2.f * acc[i][1];
    o0.z = sqj[c0 + 2] - 2.f * acc[i][2];
    o0.w = sqj[c0 + 3] - 2.f * acc[i][3];
    o1.x = sqj[c0 + 4] - 2.f * acc[i][4];
    o1.y = sqj[c0 + 5] - 2.f * acc[i][5];
    o1.z = sqj[c0 + 6] - 2.f * acc[i][6];
    o1.w = sqj[c0 + 7] - 2.f * acc[i][7];
    size_t base = (((size_t)(b << 10) + i0 + r0 + i) << 10) + j0 + c0;
    *(float4*)&g_dist[base]     = o0;
    *(float4*)&g_dist[base + 4] = o1;
  }
}

// ---------------- top-16: warp per row, register-resident ----------------
__global__ __launch_bounds__(256) void topk_kernel() {
  int gw = (blockIdx.x << 3) + (threadIdx.x >> 5);   // row 0..65535
  int lane = threadIdx.x & 31;
  const float* src = g_dist + ((size_t)gw << 10);
  float v[32];
#pragma unroll
  for (int q = 0; q < 32; q++) v[q] = src[(q << 5) + lane];
  float bv = v[0]; int bq = 0;
#pragma unroll
  for (int q = 1; q < 32; q++) if (v[q] < bv) { bv = v[q]; bq = q; }
  int bidx = (bq << 5) + lane;
#pragma unroll 1
  for (int it = 0; it < 16; it++) {
    float wv = bv; int wi = bidx;
#pragma unroll
    for (int o = 16; o; o >>= 1) {
      float ov = __shfl_down_sync(0xffffffffu, wv, o);
      int   oi = __shfl_down_sync(0xffffffffu, wi, o);
      if (ov < wv || (ov == wv && oi < wi)) { wv = ov; wi = oi; }
    }
    wi = __shfl_sync(0xffffffffu, wi, 0);
    if (lane == 0) g_idx[(gw << 4) + it] = wi;
    if ((wi & 31) == lane) {
      int qr = wi >> 5;
#pragma unroll
      for (int q = 0; q < 32; q++) if (q == qr) v[q] = 3.402823466e38f;
      bv = v[0]; bq = 0;
#pragma unroll
      for (int q = 1; q < 32; q++) if (v[q] < bv) { bv = v[q]; bq = q; }
      bidx = (bq << 5) + lane;
    }
  }
}

// ---------------- point-level A/P precompute ----------------
__global__ __launch_bounds__(256) void prec1_kernel(const float* __restrict__ x,
                                                    const float* __restrict__ w1,
                                                    const float* __restrict__ b1) {
  int t = blockIdx.x * 256 + threadIdx.x;
  int i = t >> 4;
  int c = (t & 15) << 2;
  float xi = x[i];
  float4 wa = *(const float4*)&w1[c];
  float4 wb = *(const float4*)&w1[64 + c];
  float4 bb = *(const float4*)&b1[c];
  float4 A, P;
  A.x = xi * (wa.x - wb.x) + bb.x;  P.x = xi * wb.x;
  A.y = xi * (wa.y - wb.y) + bb.y;  P.y = xi * wb.y;
  A.z = xi * (wa.z - wb.z) + bb.z;  P.z = xi * wb.z;
  A.w = xi * (wa.w - wb.w) + bb.w;  P.w = xi * wb.w;
  *(float4*)&g_A[(size_t)i * 64 + c] = A;
  *(float4*)&g_P[(size_t)i * 64 + c] = P;
}

__global__ __launch_bounds__(256) void prec64_kernel(int featOff,
                                                     const float* __restrict__ w1,
                                                     const float* __restrict__ b1) {
  __shared__ float xs[64][36];
  __shared__ float wd[32][64];
  __shared__ float wb[32][64];
  int tid = threadIdx.x;
  int row0 = blockIdx.x * 64;
  int rb = tid & 15, cb = tid >> 4;
  int r0 = rb * 4, c0 = cb * 4;
  float accA[4][4] = {}, accP[4][4] = {};

  for (int kc = 0; kc < 64; kc += 32) {
    __syncthreads();
    for (int t = tid; t < 2048; t += 256) {
      int rr = t >> 5, dd = t & 31;
      xs[rr][dd] = g_feat[(size_t)(row0 + rr) * 192 + featOff + kc + dd];
    }
    for (int t = tid; t < 2048; t += 256) {
      int kk = t >> 6, cc = t & 63;
      float bw = w1[(size_t)(64 + kc + kk) * 64 + cc];
      wb[kk][cc] = bw;
      wd[kk][cc] = w1[(size_t)(kc + kk) * 64 + cc] - bw;
    }
    __syncthreads();
#pragma unroll
    for (int k = 0; k < 32; k += 4) {
      float a[4][4];
#pragma unroll
      for (int i = 0; i < 4; i++) {
        float4 v = *(const float4*)&xs[r0 + i][k];
        a[i][0] = v.x; a[i][1] = v.y; a[i][2] = v.z; a[i][3] = v.w;
      }
#pragma unroll
      for (int kk = 0; kk < 4; kk++)
#pragma unroll
        for (int cc = 0; cc < 4; cc++) {
          float wdv = wd[k + kk][c0 + cc];
          float wbv = wb[k + kk][c0 + cc];
#pragma unroll
          for (int i = 0; i < 4; i++) {
            accA[i][cc] += a[i][kk] * wdv;
            accP[i][cc] += a[i][kk] * wbv;
          }
        }
    }
  }
#pragma unroll
  for (int i = 0; i < 4; i++)
#pragma unroll
    for (int cc = 0; cc < 4; cc++) {
      int r = row0 + r0 + i, c = c0 + cc;
      g_A[(size_t)r * 64 + c] = accA[i][cc] + b1[c];
      g_P[(size_t)r * 64 + c] = accP[i][cc];
    }
}

// ---------------- fused edge kernel ----------------
// 8 points x 16 edges = 128 h1 rows (transposed smem), 128x64 GEMM @ 8x8 micro,
// segmented max epilogue.
__global__ __launch_bounds__(128, 4) void edge_kernel(const float* __restrict__ w2,
                                                      const float* __restrict__ b2,
                                                      int outOff) {
  __shared__ float h1T[64][132];
  __shared__ float w2s[32][68];   // reused as red[16][68] after GEMM
  int tid = threadIdx.x;
  int p0 = blockIdx.x << 3;

  // build h1 rows transposed: h1T[d][r] = relu(A[i(r)][d] + P[j(r)][d])
  {
    int r = tid;                // one row per thread
    int p = r >> 4, e = r & 15;
    int gi = p0 + p;
    int bb = gi >> 10;
    int j = g_idx[(gi << 4) + e];
    const float* Ar = g_A + ((size_t)gi << 6);
    const float* Pr = g_P + ((size_t)((bb << 10) + j) << 6);
#pragma unroll
    for (int d = 0; d < 64; d += 4) {
      float4 av = *(const float4*)(Ar + d);
      float4 pv = *(const float4*)(Pr + d);
      h1T[d + 0][r] = fmaxf(av.x + pv.x, 0.f);
      h1T[d + 1][r] = fmaxf(av.y + pv.y, 0.f);
      h1T[d + 2][r] = fmaxf(av.z + pv.z, 0.f);
      h1T[d + 3][r] = fmaxf(av.w + pv.w, 0.f);
    }
  }

  int rb = tid & 15, cb = tid >> 4;   // cb 0..7
  int r0 = rb << 3, c0 = cb << 3;
  float acc[8][8];
#pragma unroll
  for (int i = 0; i < 8; i++)
#pragma unroll
    for (int j = 0; j < 8; j++) acc[i][j] = 0.f;

  for (int kc = 0; kc < 64; kc += 32) {
    __syncthreads();
    for (int t = tid; t < 512; t += 128) {
      int k = t >> 4, cg = (t & 15) << 2;
      *(float4*)&w2s[k][cg] = *(const float4*)&w2[((size_t)(kc + k) << 6) + cg];
    }
    __syncthreads();
#pragma unroll
    for (int k = 0; k < 32; k++) {
      float a[8], bv[8];
      *(float4*)&a[0]  = *(const float4*)&h1T[kc + k][r0];
      *(float4*)&a[4]  = *(const float4*)&h1T[kc + k][r0 + 4];
      *(float4*)&bv[0] = *(const float4*)&w2s[k][c0];
      *(float4*)&bv[4] = *(const float4*)&w2s[k][c0 + 4];
#pragma unroll
      for (int i = 0; i < 8; i++)
#pragma unroll
        for (int j = 0; j < 8; j++) acc[i][j] += a[i] * bv[j];
    }
  }
  __syncthreads();               // all w2s reads done -> reuse as red
  float* red = &w2s[0][0];       // red[row] at red[row*68 + c], rows 0..15

  // this thread's 8 rows are edges of point rb>>1 (half of its 16 edges)
#pragma unroll
  for (int j = 0; j < 8; j++) {
    float m = acc[0][j];
#pragma unroll
    for (int i = 1; i < 8; i++) m = fmaxf(m, acc[i][j]);
    red[rb * 68 + c0 + j] = m;
  }
  __syncthreads();

  // combine halves: 8 points x 64 cols = 512 outputs, float4 per thread
  {
    int p = tid >> 4;
    int c = (tid & 15) << 2;
    float4 m0 = *(const float4*)&red[(2 * p) * 68 + c];
    float4 m1 = *(const float4*)&red[(2 * p + 1) * 68 + c];
    float4 bb4 = *(const float4*)&b2[c];
    float4 o;
    o.x = fmaxf(m0.x, m1.x) + bb4.x;
    o.y = fmaxf(m0.y, m1.y) + bb4.y;
    o.z = fmaxf(m0.z, m1.z) + bb4.z;
    o.w = fmaxf(m0.w, m1.w) + bb4.w;
    *(float4*)&g_feat[(size_t)(p0 + p) * 192 + outOff + c] = o;
  }
}

// ---------------- MLP1: 192 -> 128, 128x128 tiles, 8x8 micro ----------------
__global__ __launch_bounds__(256, 2) void mlp1_kernel(const float* __restrict__ W,
                                                      const float* __restrict__ bias) {
  __shared__ float xT[32][132];
  __shared__ float ws[32][132];
  int tid = threadIdx.x;
  int row0 = blockIdx.x << 7;
  int rb = tid & 15, cb = tid >> 4;
  int r0 = rb << 3, c0 = cb << 3;
  float acc[8][8];
#pragma unroll
  for (int i = 0; i < 8; i++)
#pragma unroll
    for (int j = 0; j < 8; j++) acc[i][j] = 0.f;

  for (int kc = 0; kc < 192; kc += 32) {
    __syncthreads();
#pragma unroll
    for (int t = tid; t < 1024; t += 256) {
      int r = t >> 3, dg = (t & 7) << 2;
      float4 v = *(const float4*)&g_feat[(size_t)(row0 + r) * 192 + kc + dg];
      xT[dg + 0][r] = v.x; xT[dg + 1][r] = v.y;
      xT[dg + 2][r] = v.z; xT[dg + 3][r] = v.w;
    }
#pragma unroll
    for (int t = tid; t < 1024; t += 256) {
      int k = t >> 5, cg = (t & 31) << 2;
      *(float4*)&ws[k][cg] = *(const float4*)&W[(size_t)(kc + k) * 128 + cg];
    }
    __syncthreads();
#pragma unroll
    for (int k = 0; k < 32; k++) {
      float a[8], bv[8];
      *(float4*)&a[0]  = *(const float4*)&xT[k][r0];
      *(float4*)&a[4]  = *(const float4*)&xT[k][r0 + 4];
      *(float4*)&bv[0] = *(const float4*)&ws[k][c0];
      *(float4*)&bv[4] = *(const float4*)&ws[k][c0 + 4];
#pragma unroll
      for (int i = 0; i < 8; i++)
#pragma unroll
        for (int j = 0; j < 8; j++) acc[i][j] += a[i] * bv[j];
    }
  }
#pragma unroll
  for (int i = 0; i < 8; i++) {
    float4 o0, o1;
    o0.x = fmaxf(acc[i][0] + bias[c0 + 0], 0.f);
    o0.y = fmaxf(acc[i][1] + bias[c0 + 1], 0.f);
    o0.z = fmaxf(acc[i][2] + bias[c0 + 2], 0.f);
    o0.w = fmaxf(acc[i][3] + bias[c0 + 3], 0.f);
    o1.x = fmaxf(acc[i][4] + bias[c0 + 4], 0.f);
    o1.y = fmaxf(acc[i][5] + bias[c0 + 5], 0.f);
    o1.z = fmaxf(acc[i][6] + bias[c0 + 6], 0.f);
    o1.w = fmaxf(acc[i][7] + bias[c0 + 7], 0.f);
    size_t base = ((size_t)(row0 + r0 + i) << 7) + c0;
    *(float4*)&g_h1[base]     = o0;
    *(float4*)&g_h1[base + 4] = o1;
  }
}

// ---------------- small MLP GEMMs (unchanged micro) ----------------
template <int K, int N, bool RELU>
__global__ __launch_bounds__(256) void gemm_kernel(int xsel, int sx,
                                                   const float* __restrict__ W,
                                                   const float* __restrict__ bias,
                                                   int osel, int so) {
  constexpr int CT = N / 16;
  __shared__ float xs[64][36];
  __shared__ float ws[32][N];
  const float* X = buf_sel(xsel);
  float* out = buf_sel(osel);
  int tid = threadIdx.x;
  int row0 = blockIdx.x * 64;
  int rb = tid & 15, cb = tid >> 4;
  int r0 = rb * 4, c0 = cb * CT;
  float acc[4][CT];
#pragma unroll
  for (int i = 0; i < 4; i++)
#pragma unroll
    for (int c = 0; c < CT; c++) acc[i][c] = 0.f;

  for (int kc = 0; kc < K; kc += 32) {
    __syncthreads();
    for (int t = tid; t < 2048; t += 256) {
      int rr = t >> 5, dd = t & 31;
      xs[rr][dd] = X[(size_t)(row0 + rr) * sx + kc + dd];
    }
    for (int t = tid; t < 32 * N; t += 256) {
      int kk = t / N, cc = t % N;
      ws[kk][cc] = W[(size_t)(kc + kk) * N + cc];
    }
    __syncthreads();
#pragma unroll
    for (int k = 0; k < 32; k += 4) {
      float a[4][4];
#pragma unroll
      for (int i = 0; i < 4; i++) {
        float4 v = *(const float4*)&xs[r0 + i][k];
        a[i][0] = v.x; a[i][1] = v.y; a[i][2] = v.z; a[i][3] = v.w;
      }
#pragma unroll
      for (int kk = 0; kk < 4; kk++)
#pragma unroll
        for (int cc = 0; cc < CT; cc++) {
          float wv = ws[k + kk][c0 + cc];
#pragma unroll
          for (int i = 0; i < 4; i++) acc[i][cc] += a[i][kk] * wv;
        }
    }
  }
#pragma unroll
  for (int i = 0; i < 4; i++)
#pragma unroll
    for (int cc = 0; cc < CT; cc++) {
      float v = acc[i][cc] + bias[c0 + cc];
      if (RELU) v = fmaxf(v, 0.f);
      out[(size_t)(row0 + r0 + i) * so + c0 + cc] = v;
    }
}

// ---------------- final layer (32 -> 2) + log_softmax ----------------
__global__ __launch_bounds__(256) void final_kernel(const float* __restrict__ w4,
                                                    const float* __restrict__ b4,
                                                    float* __restrict__ out) {
  int i = blockIdx.x * 256 + threadIdx.x;
  const float* h = g_h3 + (size_t)i * 32;
  float z0 = b4[0], z1 = b4[1];
#pragma unroll
  for (int k = 0; k < 32; k += 4) {
    float4 v = *(const float4*)&h[k];
    z0 += v.x * w4[(k + 0) * 2 + 0];  z1 += v.x * w4[(k + 0) * 2 + 1];
    z0 += v.y * w4[(k + 1) * 2 + 0];  z1 += v.y * w4[(k + 1) * 2 + 1];
    z0 += v.z * w4[(k + 2) * 2 + 0];  z1 += v.z * w4[(k + 2) * 2 + 1];
    z0 += v.w * w4[(k + 3) * 2 + 0];  z1 += v.w * w4[(k + 3) * 2 + 1];
  }
  float m = fmaxf(z0, z1);
  float l = m + logf(expf(z0 - m) + expf(z1 - m));
  out[2 * i + 0] = z0 - l;
  out[2 * i + 1] = z1 - l;
}

// ---------------- launch ----------------
extern "C" void kernel_launch(void* const* d_in, const int* in_sizes, int n_in,
                              void* d_out, int out_size) {
  const float* x    = (const float*)d_in[0];
  const float* c1w1 = (const float*)d_in[1];
  const float* c1b1 = (const float*)d_in[2];
  const float* c1w2 = (const float*)d_in[3];
  const float* c1b2 = (const float*)d_in[4];
  const float* c2w1 = (const float*)d_in[5];
  const float* c2b1 = (const float*)d_in[6];
  const float* c2w2 = (const float*)d_in[7];
  const float* c2b2 = (const float*)d_in[8];
  const float* c3w1 = (const float*)d_in[9];
  const float* c3b1 = (const float*)d_in[10];
  const float* c3w2 = (const float*)d_in[11];
  const float* c3b2 = (const float*)d_in[12];
  const float* mw1  = (const float*)d_in[13];
  const float* mb1  = (const float*)d_in[14];
  const float* mw2  = (const float*)d_in[15];
  const float* mb2  = (const float*)d_in[16];
  const float* mw3  = (const float*)d_in[17];
  const float* mb3  = (const float*)d_in[18];
  const float* mw4  = (const float*)d_in[19];
  const float* mb4  = (const float*)d_in[20];
  float* out = (float*)d_out;

  // ---- EdgeConv 1 (d_in = 1) ----
  dist1_kernel<<<65536, 256>>>(x);
  topk_kernel<<<8192, 256>>>();
  prec1_kernel<<<4096, 256>>>(x, c1w1, c1b1);
  edge_kernel<<<8192, 128>>>(c1w2, c1b2, 0);

  // ---- EdgeConv 2 (on x1, d_in = 64) ----
  dist64_kernel<<<dim3(8, 8, 64), 256>>>(0);
  topk_kernel<<<8192, 256>>>();
  prec64_kernel<<<1024, 256>>>(0, c2w1, c2b1);
  edge_kernel<<<8192, 128>>>(c2w2, c2b2, 64);

  // ---- EdgeConv 3 (on x2, d_in = 64) ----
  dist64_kernel<<<dim3(8, 8, 64), 256>>>(64);
  topk_kernel<<<8192, 256>>>();
  prec64_kernel<<<1024, 256>>>(64, c3w1, c3b1);
  edge_kernel<<<8192, 128>>>(c3w2, c3b2, 128);

  // ---- MLP head ----
  mlp1_kernel<<<512, 256>>>(mw1, mb1);
  gemm_kernel<128, 64, true><<<1024, 256>>>(1, 128, mw2, mb2, 2, 64);
  gemm_kernel<64, 32, true><<<1024, 256>>>(2, 64, mw3, mb3, 3, 32);
  final_kernel<<<256, 256>>>(mw4, mb4, out);
}